// round 13
// baseline (speedup 1.0000x reference)
#include <cuda_runtime.h>
#include <math.h>

namespace {

constexpr int P     = 13;
constexpr int NS    = 1 << P;      // 8192 amplitudes
constexpr int TPB   = 512;
constexpr int D     = 64;
constexpr int NWARP = TPB / 32;

struct c32 { float x, y; };
typedef unsigned long long u64;

__device__ __forceinline__ c32 cmul(c32 a, c32 b) {
    return { fmaf(a.x, b.x, -a.y * b.y), fmaf(a.x, b.y, a.y * b.x) };
}

// ---------------- packed f32x2 helpers ----------------
__device__ __forceinline__ u64 pk2(float x, float y) {
    u64 r; asm("mov.b64 %0, {%1, %2};" : "=l"(r) : "f"(x), "f"(y)); return r;
}
__device__ __forceinline__ void upk2(u64 v, float& x, float& y) {
    asm("mov.b64 {%0, %1}, %2;" : "=f"(x), "=f"(y) : "l"(v));
}
__device__ __forceinline__ u64 swp2(u64 v) {
    u64 r;
    asm("{ .reg .b32 lo, hi; mov.b64 {lo, hi}, %1; mov.b64 %0, {hi, lo}; }"
        : "=l"(r) : "l"(v));
    return r;
}
__device__ __forceinline__ u64 mul2(u64 a, u64 b) {
    u64 r; asm("mul.rn.f32x2 %0, %1, %2;" : "=l"(r) : "l"(a), "l"(b)); return r;
}
__device__ __forceinline__ u64 fma2(u64 a, u64 b, u64 c) {
    u64 r; asm("fma.rn.f32x2 %0, %1, %2, %3;" : "=l"(r) : "l"(a), "l"(b), "l"(c)); return r;
}
__device__ __forceinline__ u64 splat2(float v) {
    u64 r; asm("mov.b64 %0, {%1, %1};" : "=l"(r) : "f"(v)); return r;
}
// v * Phi where table entry e = {Phi.x, Phi.x, -Phi.y, Phi.y}
__device__ __forceinline__ u64 diag_mul(u64 v, float4 e) {
    u64 xx = pk2(e.x, e.y), yn = pk2(e.z, e.w);
    return fma2(v, xx, mul2(swp2(v), yn));
}

// ---------------- compile-time GF(2) machinery ----------------

__host__ __device__ constexpr int cg_cnot(int i, int x) {
    int cb = P - 1 - i;
    int tb = P - 1 - ((i + 1) % P);
    return ((x >> cb) & 1) ? (x ^ (1 << tb)) : x;
}
__host__ __device__ constexpr int cGmap(int y) {
    for (int i = P - 1; i >= 0; --i) y = cg_cnot(i, y);
    return y;
}
__host__ __device__ constexpr int cGinv(int y) {
    for (int i = 0; i < P; i++) y = cg_cnot(i, y);
    return y;
}
__host__ __device__ constexpr int cpop(int x) { int c = 0; for (int i = 0; i < 16; i++) c += (x >> i) & 1; return c; }
__host__ __device__ constexpr int cctz(int x) { for (int i = 0; i < 16; i++) if ((x >> i) & 1) return i; return -1; }

struct QCData {
    int m2[P];            // layer-2 pair masks  G(e_w)
    int r2[P];            // layer-2 orientation masks (rows of G^-1)
    int rm[P];            // measurement parity masks (rows of G^-2)
    int npos[3][9];       // non-pivot bit positions per batch (ascending)
    int combo[3][16];     // XOR offsets of the 16 coset members
    int lm[3][4];         // local 4-bit pair pattern per gate
    int lml[3][4];        // lowest set bit of lm (canonical selector)
    int lr[3][4];         // local parity pattern per gate
    int rw[3][4];         // full orientation mask per gate (for px)
    int odm[8];           // measurement: per-jj orientation delta (compile-time)
    int mg[4];            // measurement: WHT sig generators
    int kw[P];            // measurement: WHT coefficient index per wire
    int didx01[16];       // T01 index offsets per combo[0][j]
    int didx12[16];       // T12 index offsets per combo[1][j]
    int didxp2[16];       // Tpre2 index offsets per combo[2][j]
    int didxm[16];        // Tm index offsets per (jj,side)
};

__host__ __device__ constexpr QCData make_qc() {
    QCData q{};
    for (int w = 0; w < P; w++) {
        q.m2[w] = cGmap(1 << (P - 1 - w));
        int r = 0, rm = 0;
        for (int p = 0; p < P; p++) {
            int gi  = cGinv(1 << p);
            int gi2 = cGinv(gi);
            r  |= ((gi  >> (P - 1 - w)) & 1) << p;
            rm |= ((gi2 >> (P - 1 - w)) & 1) << p;
        }
        q.r2[w] = r; q.rm[w] = rm;
    }
    for (int b = 0; b < 3; b++) {
        int f[4] = {}, piv[4] = {};
        for (int i = 0; i < 4; i++) f[i] = q.m2[4 * b + i];
        for (int i = 0; i < 4; i++) {
            for (int j = 0; j < i; j++) if ((f[i] >> piv[j]) & 1) f[i] ^= f[j];
            piv[i] = cctz(f[i]);
            for (int j = 0; j < i; j++) if ((f[j] >> piv[i]) & 1) f[j] ^= f[i];
        }
        int np = 0;
        for (int bit = 0; bit < P; bit++) {
            bool isp = false;
            for (int i = 0; i < 4; i++) if (piv[i] == bit) isp = true;
            if (!isp) q.npos[b][np++] = bit;
        }
        for (int j = 0; j < 16; j++) {
            int c = 0;
            for (int i = 0; i < 4; i++) if ((j >> i) & 1) c ^= f[i];
            q.combo[b][j] = c;
        }
        for (int g = 0; g < 4; g++) {
            int m = q.m2[4 * b + g], r = q.r2[4 * b + g];
            int lm = 0, lr = 0;
            for (int i = 0; i < 4; i++) {
                lm |= ((m >> piv[i]) & 1) << i;
                lr |= (cpop(f[i] & r) & 1) << i;
            }
            q.lm[b][g] = lm;
            q.lml[b][g] = lm & (-lm);
            q.lr[b][g] = lr;
            q.rw[b][g] = r;
        }
    }
    // measurement constants
    {
        int m12 = q.m2[12], r12 = q.r2[12];
        for (int jj = 0; jj < 8; jj++) q.odm[jj] = cpop((jj << 10) & r12) & 1;
        for (int i = 0; i < 4; i++) {
            int v = (i < 3) ? (1024 << i) : m12;
            int sgn = 0;
            for (int w = 0; w < P; w++) sgn |= (cpop(v & q.rm[w]) & 1) << w;
            q.mg[i] = sgn;
        }
        for (int w = 0; w < P; w++) {
            int k = 0;
            for (int i = 0; i < 4; i++) k |= ((q.mg[i] >> w) & 1) << i;
            q.kw[w] = k;
        }
    }
    // diagonal-table index offsets
    for (int j = 0; j < 16; j++) {
        int c0 = q.combo[0][j], c1 = q.combo[1][j], c2 = q.combo[2][j];
        int v0 = 0, v1 = 0, v2 = 0;
        for (int k = 0; k < 4; k++) {
            v0 |= (cpop(c0 & q.r2[8 + k]) & 1) << k;
            v0 |= (cpop(c0 & q.r2[k]) & 1) << (4 + k);
            v1 |= (cpop(c1 & q.r2[k]) & 1) << k;
            v1 |= (cpop(c1 & q.r2[4 + k]) & 1) << (4 + k);
            v2 |= (cpop(c2 & q.r2[8 + k]) & 1) << k;
        }
        q.didx01[j] = v0; q.didx12[j] = v1; q.didxp2[j] = v2;
    }
    for (int jj = 0; jj < 8; jj++)
        for (int side = 0; side < 2; side++) {
            int d = (jj << 10) ^ (side ? q.m2[12] : 0);
            int v = 0;
            for (int k = 0; k < 4; k++) v |= (cpop(d & q.r2[4 + k]) & 1) << k;
            v |= (cpop(d & q.r2[12]) & 1) << 4;
            q.didxm[jj * 2 + side] = v;
        }
    return q;
}

// host-side structural checks only
constexpr QCData QC_HOST = make_qc();
__host__ __device__ constexpr int batch2_support() {
    int s = 0;
    for (int j = 0; j < 16; j++) s |= QC_HOST.combo[2][j];
    return s;
}
static_assert((QC_HOST.m2[12] & 1) == 1, "insert for final gate must be <<1");
static_assert(QC_HOST.npos[2][0] == 4 && QC_HOST.npos[2][8] == 12, "batch2 coset must be low-bit");
static_assert((batch2_support() & ~0x1F) == 0, "batch2 combos must live in bits 0..4");

// SMEM bank-conflict swizzle: XOR bits[7:4] into bits[3:0]. Bijection on [0,8192).
__device__ __forceinline__ int sw(int y) { return y ^ ((y >> 4) & 0xF); }

// ---------------- SMEM layout (floats; 16B alignment for tables) ----------------
constexpr int SM_S    = 0;          // 8192 u64 state  (16384 floats)
constexpr int SM_T01  = 16384;      // 256 x float4   (1024)
constexpr int SM_T12  = 17408;      // 256 x float4   (1024)
constexpr int SM_TP2  = 18432;      // 16  x float4   (64)
constexpr int SM_TM   = 18496;      // 32  x float4   (128)
constexpr int SM_COLA = 18624;      // 13*2 c32       (52)
constexpr int SM_GCS  = 18676;      // 13 float2      (26, +2 pad)
constexpr int SM_GPH  = 18704;      // 13*4 floats (pA,pB per gate) (52)
constexpr int SM_WSUM = 18756;      // NWARP*13       (208)
constexpr int SM_EXPV = 18964;      // 13
constexpr int SMEM_BYTES = (18964 + 13 + 3) * 4;

// Real-rotation batch: 4 gates, pure packed FMA, zero swaps.
template <int B>
__device__ __forceinline__ void apply_batch_rot(u64* __restrict__ reg,
                                                const float2* __restrict__ gcs, int x)
{
    constexpr QCData qc = make_qc();
#pragma unroll
    for (int g = 0; g < 4; g++) {
        const int w = 4 * B + g;
        const float c = gcs[w].x, s = gcs[w].y;
        const bool px = (__popc(x & qc.rw[B][g]) & 1) != 0;
        const float se = px ? -s : s;
        const u64 cc = splat2(c), sp = splat2(se), sn = splat2(-se);
#pragma unroll
        for (int j = 0; j < 16; j++) {
            if (j & qc.lml[B][g]) continue;
            const int jp  = j ^ qc.lm[B][g];
            const bool pc = (cpop(j & qc.lr[B][g]) & 1) != 0;
            const u64 sj  = pc ? sn : sp;   // for out[jp]
            const u64 sjn = pc ? sp : sn;   // for out[j]
            const u64 va = reg[j], vb = reg[jp];
            reg[j]  = fma2(vb, sjn, mul2(va, cc));
            reg[jp] = fma2(va, sj,  mul2(vb, cc));
        }
    }
}

// Batch with leading merged diagonal (table lookup) + real rotations.
template <int B>
__device__ __forceinline__ void do_batch_d(u64* __restrict__ s64,
                                           const float2* __restrict__ gcs,
                                           const float4* __restrict__ tbl, int tid)
{
    constexpr QCData qc = make_qc();
    int x = 0;
#pragma unroll
    for (int i = 0; i < 9; i++) x |= ((tid >> i) & 1) << qc.npos[B][i];

    u64 reg[16];
#pragma unroll
    for (int j = 0; j < 16; j++) reg[j] = s64[sw(x ^ qc.combo[B][j])];

    int base = 0;
    if (B == 0) {
#pragma unroll
        for (int k = 0; k < 4; k++) {
            base |= (__popc(x & qc.r2[8 + k]) & 1) << k;
            base |= (__popc(x & qc.r2[k]) & 1) << (4 + k);
        }
    } else {
#pragma unroll
        for (int k = 0; k < 4; k++) {
            base |= (__popc(x & qc.r2[k]) & 1) << k;
            base |= (__popc(x & qc.r2[4 + k]) & 1) << (4 + k);
        }
    }
#pragma unroll
    for (int j = 0; j < 16; j++) {
        const int off = (B == 0) ? qc.didx01[j] : qc.didx12[j];
        reg[j] = diag_mul(reg[j], tbl[base ^ off]);
    }

    apply_batch_rot<B>(reg, gcs, x);

#pragma unroll
    for (int j = 0; j < 16; j++) s64[sw(x ^ qc.combo[B][j])] = reg[j];
}

__global__ void __launch_bounds__(TPB, 2)
qlc_kernel(const float* __restrict__ h,
           const float* __restrict__ enc_w,
           const float* __restrict__ enc_b,
           const float* __restrict__ qw,
           const float* __restrict__ dec_w,
           const float* __restrict__ alpha,
           float* __restrict__ out)
{
    extern __shared__ float smemf[];
    u64*    s64  = (u64*)(smemf + SM_S);
    float4* T01  = (float4*)(smemf + SM_T01);
    float4* T12  = (float4*)(smemf + SM_T12);
    float4* TP2  = (float4*)(smemf + SM_TP2);
    float4* TM   = (float4*)(smemf + SM_TM);
    c32*    colA = (c32*)(smemf + SM_COLA);
    float2* gcs  = (float2*)(smemf + SM_GCS);
    float*  gphf = smemf + SM_GPH;          // per gate: {pA.x, pA.y, pB.x, pB.y}
    float*  wsum = smemf + SM_WSUM;
    float*  expv = smemf + SM_EXPV;

    const int n = blockIdx.x, tid = threadIdx.x, wid = tid >> 5, lane = tid & 31;

    // ================= Phase A =================
    // warps 0..12: per-sample angles + fused (enc+L1) column for own wire.
    // warp 13: shared-weight layer-2 gates -> ZYZ (c,s,pA,pB) + small tables.
    if (wid < P) {
        const float* hrow = h + (n * P + wid) * D;
        float h0 = hrow[lane], h1 = hrow[lane + 32];
        float aa0 = 0.f, aa1 = 0.f, aa2 = 0.f;
#pragma unroll
        for (int a = 0; a < 3; a++) {
            float v = h0 * enc_w[a * D + lane] + h1 * enc_w[a * D + lane + 32];
#pragma unroll
            for (int off = 16; off; off >>= 1)
                v += __shfl_xor_sync(0xffffffffu, v, off);
            if (a == 0) aa0 = v; else if (a == 1) aa1 = v; else aa2 = v;
        }
        if (lane == 0) {
            const int w = wid;
            float a0 = aa0 + enc_b[0], a1 = aa1 + enc_b[1], a2 = aa2 + enc_b[2];
            float q0 = qw[w * 3 + 0], q1 = qw[w * 3 + 1], q2 = qw[w * 3 + 2];  // layer 0
            float sA, cA; sincosf(0.5f * a0, &sA, &cA);
            c32 v0 = { cA, 0.f }, v1 = { 0.f, -sA };                 // RX col0
            float sB, cB; sincosf(0.5f * a1, &sB, &cB);              // RY
            c32 t0 = { cB * v0.x - sB * v1.x, cB * v0.y - sB * v1.y };
            c32 t1 = { sB * v0.x + cB * v1.x, sB * v0.y + cB * v1.y };
            float sC, cC; sincosf(0.5f * a2, &sC, &cC);              // RZ
            v0 = cmul({ cC, -sC }, t0); v1 = cmul({ cC, sC }, t1);
            float s0, c0; sincosf(0.5f * q0, &s0, &c0);              // RY
            t0 = { c0 * v0.x - s0 * v1.x, c0 * v0.y - s0 * v1.y };
            t1 = { s0 * v0.x + c0 * v1.x, s0 * v0.y + c0 * v1.y };
            float s1, c1; sincosf(0.5f * q1, &s1, &c1);              // RZ
            v0 = cmul({ c1, -s1 }, t0); v1 = cmul({ c1, s1 }, t1);
            float s2, c2; sincosf(0.5f * q2, &s2, &c2);              // RY
            t0 = { c2 * v0.x - s2 * v1.x, c2 * v0.y - s2 * v1.y };
            t1 = { s2 * v0.x + c2 * v1.x, s2 * v0.y + c2 * v1.y };
            colA[w * 2 + 0] = t0; colA[w * 2 + 1] = t1;
        }
    } else if (wid == 13) {
        if (lane < P) {
            const int w = lane;
            float q0 = qw[(P + w) * 3 + 0], q1 = qw[(P + w) * 3 + 1], q2 = qw[(P + w) * 3 + 2];
            float s0, c0; sincosf(0.5f * q0, &s0, &c0);
            float s1, c1; sincosf(0.5f * q1, &s1, &c1);
            float s2, c2; sincosf(0.5f * q2, &s2, &c2);
            // U = RY(q2) * RZ(q1) * RY(q0)
            c32 e0 = { c1, -s1 }, e1 = { c1, s1 };
            c32 m00 = {  e0.x * c0,  e0.y * c0 }, m01 = { -e0.x * s0, -e0.y * s0 };
            c32 m10 = {  e1.x * s0,  e1.y * s0 }, m11 = {  e1.x * c0,  e1.y * c0 };
            c32 u00 = { c2 * m00.x - s2 * m10.x, c2 * m00.y - s2 * m10.y };
            c32 u10 = { s2 * m00.x + c2 * m10.x, s2 * m00.y + c2 * m10.y };
            (void)m01; (void)m11;
            // ZYZ: U = RZ(alpha) RY(theta) RZ(beta), SU(2)
            float cm = sqrtf(u00.x * u00.x + u00.y * u00.y);
            float sm = sqrtf(u10.x * u10.x + u10.y * u10.y);
            float ps1 = atan2f(u00.y, u00.x);
            float ps2 = atan2f(u10.y, u10.x);
            float al = ps2 - ps1, be = -(ps1 + ps2);
            float sa, ca; sincosf(0.5f * al, &sa, &ca);
            float sb, cb2; sincosf(0.5f * be, &sb, &cb2);
            gcs[w] = { cm, sm };
            gphf[w * 4 + 0] = ca;  gphf[w * 4 + 1] = -sa;   // pA = e^{-i a/2}
            gphf[w * 4 + 2] = cb2; gphf[w * 4 + 3] = -sb;   // pB = e^{-i b/2}
        }
        __syncwarp();
        // Tpre2: beta phases of gates 8..11 (4 bits)
        if (lane < 16) {
            c32 acc = { 1.f, 0.f };
#pragma unroll
            for (int k = 0; k < 4; k++) {
                c32 p = { gphf[(8 + k) * 4 + 2], gphf[(8 + k) * 4 + 3] };
                if ((lane >> k) & 1) p.y = -p.y;
                acc = cmul(acc, p);
            }
            TP2[lane] = { acc.x, acc.x, -acc.y, acc.y };
        }
        // Tm: alpha of gates 4..7 (bits 0..3) + beta of gate 12 (bit 4)
        {
            c32 acc = { 1.f, 0.f };
#pragma unroll
            for (int k = 0; k < 4; k++) {
                c32 p = { gphf[(4 + k) * 4 + 0], gphf[(4 + k) * 4 + 1] };
                if ((lane >> k) & 1) p.y = -p.y;
                acc = cmul(acc, p);
            }
            c32 p = { gphf[12 * 4 + 2], gphf[12 * 4 + 3] };
            if ((lane >> 4) & 1) p.y = -p.y;
            acc = cmul(acc, p);
            TM[lane] = { acc.x, acc.x, -acc.y, acc.y };
        }
    }
    __syncthreads();

    // ================= Phase C: big tables + construction + batch2 =================
    {
        // T01[i]: alpha(8..11) bits 0..3, beta(0..3) bits 4..7
        // T12[i]: alpha(0..3) bits 0..3, beta(4..7) bits 4..7
        const int i = tid & 255;
        c32 acc = { 1.f, 0.f };
        if (tid < 256) {
#pragma unroll
            for (int k = 0; k < 4; k++) {
                c32 p = { gphf[(8 + k) * 4 + 0], gphf[(8 + k) * 4 + 1] };
                if ((i >> k) & 1) p.y = -p.y;
                acc = cmul(acc, p);
            }
#pragma unroll
            for (int k = 0; k < 4; k++) {
                c32 p = { gphf[k * 4 + 2], gphf[k * 4 + 3] };
                if ((i >> (4 + k)) & 1) p.y = -p.y;
                acc = cmul(acc, p);
            }
            T01[i] = { acc.x, acc.x, -acc.y, acc.y };
        } else {
#pragma unroll
            for (int k = 0; k < 4; k++) {
                c32 p = { gphf[k * 4 + 0], gphf[k * 4 + 1] };
                if ((i >> k) & 1) p.y = -p.y;
                acc = cmul(acc, p);
            }
#pragma unroll
            for (int k = 0; k < 4; k++) {
                c32 p = { gphf[(4 + k) * 4 + 2], gphf[(4 + k) * 4 + 3] };
                if ((i >> (4 + k)) & 1) p.y = -p.y;
                acc = cmul(acc, p);
            }
            T12[i] = { acc.x, acc.x, -acc.y, acc.y };
        }
    }
    {
        constexpr QCData qc = make_qc();
        // product state over stored bits (x = tid<<4 + coset)
        c32 pre = colA[0 * 2 + ((tid >> 8) & 1)];
#pragma unroll
        for (int w = 1; w < 8; w++) pre = cmul(pre, colA[w * 2 + ((tid >> (8 - w)) & 1)]);
        c32 ph[4];
#pragma unroll
        for (int t = 0; t < 4; t++)
            ph[t] = cmul(pre, cmul(colA[8 * 2 + (t >> 1)], colA[9 * 2 + (t & 1)]));
        const int t0b = tid & 1;
        c32 phe[4];
#pragma unroll
        for (int t = 0; t < 4; t++) phe[t] = t0b ? ph[t ^ 2] : ph[t];
        c32 t2[4];
#pragma unroll
        for (int t = 0; t < 4; t++) t2[t] = cmul(colA[10 * 2 + (t >> 1)], colA[11 * 2 + (t & 1)]);
        c32 pl[8];
#pragma unroll
        for (int u = 0; u < 8; u++) pl[u] = cmul(t2[u >> 1], colA[12 * 2 + (u & 1)]);

        u64 reg[16];
#pragma unroll
        for (int j = 0; j < 16; j++) {
            const int cj = qc.combo[2][j];
            const c32 v = cmul(phe[(cj >> 3) & 3], pl[cj & 7]);
            reg[j] = pk2(v.x, v.y);
        }
        const int x = tid << 4;
        // Tpre2 diagonal (beta of gates 8..11) then real rotations of batch 2
        int base = 0;
#pragma unroll
        for (int k = 0; k < 4; k++) base |= (__popc(x & qc.r2[8 + k]) & 1) << k;
#pragma unroll
        for (int j = 0; j < 16; j++) reg[j] = diag_mul(reg[j], TP2[base ^ qc.didxp2[j]]);
        apply_batch_rot<2>(reg, gcs, x);
#pragma unroll
        for (int j = 0; j < 16; j++) s64[sw(x ^ qc.combo[2][j])] = reg[j];
    }
    __syncthreads();

    do_batch_d<0>(s64, gcs, T01, tid); __syncthreads();
    do_batch_d<1>(s64, gcs, T12, tid); __syncthreads();

    // ========= measurement: Tm diag + real gate-12 rotation + WHT =========
    {
        constexpr QCData qc = make_qc();
        constexpr int m12 = qc.m2[12];
        constexpr int r12 = qc.r2[12];
        const int x0 = tid << 1;
        int basem = 0;
#pragma unroll
        for (int k = 0; k < 4; k++) basem |= (__popc(x0 & qc.r2[4 + k]) & 1) << k;
        const int pb12 = __popc(x0 & r12) & 1;
        basem |= pb12 << 4;

        const float c12 = gcs[12].x, s12 = gcs[12].y;
        const float se = pb12 ? -s12 : s12;
        const u64 cc = splat2(c12), sp = splat2(se), sn = splat2(-se);

        float p[16];
#pragma unroll
        for (int jj = 0; jj < 8; jj++) {
            const int x  = x0 ^ (jj << 10);
            const int xp = x ^ m12;
            u64 va = s64[sw(x)], vb = s64[sw(xp)];
            va = diag_mul(va, TM[basem ^ qc.didxm[jj * 2 + 0]]);
            vb = diag_mul(vb, TM[basem ^ qc.didxm[jj * 2 + 1]]);
            const bool pc = qc.odm[jj] != 0;          // compile-time
            const u64 sj  = pc ? sn : sp;
            const u64 sjn = pc ? sp : sn;
            const u64 n0 = fma2(vb, sjn, mul2(va, cc));   // amp at x
            const u64 n1 = fma2(va, sj,  mul2(vb, cc));   // amp at xp
            float n0x, n0y, n1x, n1y;
            upk2(n0, n0x, n0y); upk2(n1, n1x, n1y);
            p[jj]     = fmaf(n0x, n0x, n0y * n0y);
            p[jj | 8] = fmaf(n1x, n1x, n1y * n1y);
        }
#pragma unroll
        for (int st = 1; st < 16; st <<= 1) {
#pragma unroll
            for (int k = 0; k < 16; k++)
                if (!(k & st)) {
                    const float a = p[k], b = p[k ^ st];
                    p[k] = a + b; p[k ^ st] = a - b;
                }
        }
        int sig0 = 0;
#pragma unroll
        for (int w = 0; w < P; w++) sig0 |= (__popc(x0 & qc.rm[w]) & 1) << w;
#pragma unroll
        for (int w = 0; w < P; w++) {
            float v = p[qc.kw[w]];
            v = ((sig0 >> w) & 1) ? -v : v;
#pragma unroll
            for (int off = 16; off; off >>= 1)
                v += __shfl_xor_sync(0xffffffffu, v, off);
            if (lane == 0) wsum[wid * P + w] = v;
        }
    }
    __syncthreads();
    if (tid < P) {
        float v = 0.0f;
        for (int k = 0; k < NWARP; k++) v += wsum[k * P + tid];
        expv[tid] = v;
    }
    __syncthreads();

    // ---- decode + residual ----
    const float al = alpha[0];
    const int base = n * P * D;
    for (int e = tid; e < P * D; e += TPB) {
        const int w = e >> 6;
        const int d = e & 63;
        out[base + e] = h[base + e] + al * expv[w] * dec_w[d];
    }
}

} // anonymous namespace

extern "C" void kernel_launch(void* const* d_in, const int* in_sizes, int n_in,
                              void* d_out, int out_size)
{
    const float* h     = (const float*)d_in[0];
    const float* enc_w = (const float*)d_in[1];
    const float* enc_b = (const float*)d_in[2];
    const float* qw    = (const float*)d_in[3];
    const float* dec_w = (const float*)d_in[4];
    const float* alpha = (const float*)d_in[5];
    float* out = (float*)d_out;

    const int nsamp = in_sizes[0] / (P * D);   // B*T

    cudaFuncSetAttribute(qlc_kernel, cudaFuncAttributeMaxDynamicSharedMemorySize, SMEM_BYTES);
    qlc_kernel<<<nsamp, TPB, SMEM_BYTES>>>(h, enc_w, enc_b, qw, dec_w, alpha, out);
}